// round 4
// baseline (speedup 1.0000x reference)
#include <cuda_runtime.h>

#define BB 8
#define NN 1024
#define HH 32
#define BN (BB*NN)

// Scratch: per-node first-layer partials u[n][h] = rho*W1[0][h] + V*W1[1][h] + 0.5*b1[h]
__device__ float g_u[BN * HH];

__device__ __forceinline__ float lrelu(float v) { return fmaxf(v, 0.01f * v); }

// ---------------------------------------------------------------------------
// Kernel 1: per-node layer-1 partials.
// ---------------------------------------------------------------------------
__global__ void precompute_u(const float* __restrict__ x,
                             const float* __restrict__ Wm1,
                             const float* __restrict__ bm1) {
    int idx = blockIdx.x * blockDim.x + threadIdx.x;   // [0, BN*HH)
    int node = idx >> 5;
    int h = idx & 31;
    float rho = x[node * 2 + 0];
    float V   = x[node * 2 + 1];
    g_u[idx] = rho * Wm1[h] + V * Wm1[HH + h] + 0.5f * bm1[h];
}

// ---- fully-unrolled layer-2 step: 8 LDS.128 (broadcast) + 32 scalar FFMA ----
// All accumulators are NAMED scalar floats: dynamic indexing is impossible,
// so ptxas cannot demote anything to local memory.
#define L2STEP(K, H) do {                                                      \
    float4 wa = W2s[(K)*8+0]; c0  += wa.x*(H); c1  += wa.y*(H); c2  += wa.z*(H); c3  += wa.w*(H); \
    float4 wb = W2s[(K)*8+1]; c4  += wb.x*(H); c5  += wb.y*(H); c6  += wb.z*(H); c7  += wb.w*(H); \
    float4 wc = W2s[(K)*8+2]; c8  += wc.x*(H); c9  += wc.y*(H); c10 += wc.z*(H); c11 += wc.w*(H); \
    float4 wd = W2s[(K)*8+3]; c12 += wd.x*(H); c13 += wd.y*(H); c14 += wd.z*(H); c15 += wd.w*(H); \
    float4 we = W2s[(K)*8+4]; c16 += we.x*(H); c17 += we.y*(H); c18 += we.z*(H); c19 += we.w*(H); \
    float4 wf = W2s[(K)*8+5]; c20 += wf.x*(H); c21 += wf.y*(H); c22 += wf.z*(H); c23 += wf.w*(H); \
    float4 wg = W2s[(K)*8+6]; c24 += wg.x*(H); c25 += wg.y*(H); c26 += wg.z*(H); c27 += wg.w*(H); \
    float4 wh = W2s[(K)*8+7]; c28 += wh.x*(H); c29 += wh.y*(H); c30 += wh.z*(H); c31 += wh.w*(H); \
} while (0)

#define S3(L) s += lrelu(c##L) * W3s[L];

// ---------------------------------------------------------------------------
// Kernel 2: fused pair-MLP + A-weighted reduction + node MLP.
// One block per (b, i). 256 threads; each thread handles 4 j values.
// ---------------------------------------------------------------------------
__global__ __launch_bounds__(256) void mpnn_main(
    const float* __restrict__ x,   const float* __restrict__ A,
    const float* __restrict__ Wm2, const float* __restrict__ bm2,
    const float* __restrict__ Wm3, const float* __restrict__ bm3,
    const float* __restrict__ Wx1, const float* __restrict__ bx1,
    const float* __restrict__ Wx2, const float* __restrict__ bx2,
    const float* __restrict__ Wx3, const float* __restrict__ bx3,
    float* __restrict__ out)
{
    __shared__ float4 W2s[HH * 8];     // Wm2 row-major [k][l], 1024 floats
    __shared__ float  W3s[HH];
    __shared__ float  b2s[HH];
    __shared__ float  uis[HH];
    __shared__ float  red[256];
    __shared__ float  hsh[HH];

    const int bi  = blockIdx.x;        // b*N + i
    const int i   = bi & (NN - 1);
    const int tid = threadIdx.x;

    W2s[tid] = reinterpret_cast<const float4*>(Wm2)[tid];  // 256 float4 = 1024 floats
    if (tid < HH) {
        W3s[tid] = Wm3[tid];
        b2s[tid] = bm2[tid];
        uis[tid] = g_u[bi * HH + tid];
    }
    __syncthreads();

    const float* uB   = g_u + (bi & ~(NN - 1)) * HH;  // batch base of u
    const float* Arow = A + (long)i * NN;
    const float  bm3v = bm3[0];

    float acc = 0.0f;

    #pragma unroll 1
    for (int j = tid; j < NN; j += 256) {
        const float4* up = reinterpret_cast<const float4*>(uB + j * HH);

        // h1 = lrelu(u_i + u_j) : 32 named scalars q0..q31
        float4 t;
        t = up[0];
        float q0  = lrelu(uis[0]  + t.x), q1  = lrelu(uis[1]  + t.y),
              q2  = lrelu(uis[2]  + t.z), q3  = lrelu(uis[3]  + t.w);
        t = up[1];
        float q4  = lrelu(uis[4]  + t.x), q5  = lrelu(uis[5]  + t.y),
              q6  = lrelu(uis[6]  + t.z), q7  = lrelu(uis[7]  + t.w);
        t = up[2];
        float q8  = lrelu(uis[8]  + t.x), q9  = lrelu(uis[9]  + t.y),
              q10 = lrelu(uis[10] + t.z), q11 = lrelu(uis[11] + t.w);
        t = up[3];
        float q12 = lrelu(uis[12] + t.x), q13 = lrelu(uis[13] + t.y),
              q14 = lrelu(uis[14] + t.z), q15 = lrelu(uis[15] + t.w);
        t = up[4];
        float q16 = lrelu(uis[16] + t.x), q17 = lrelu(uis[17] + t.y),
              q18 = lrelu(uis[18] + t.z), q19 = lrelu(uis[19] + t.w);
        t = up[5];
        float q20 = lrelu(uis[20] + t.x), q21 = lrelu(uis[21] + t.y),
              q22 = lrelu(uis[22] + t.z), q23 = lrelu(uis[23] + t.w);
        t = up[6];
        float q24 = lrelu(uis[24] + t.x), q25 = lrelu(uis[25] + t.y),
              q26 = lrelu(uis[26] + t.z), q27 = lrelu(uis[27] + t.w);
        t = up[7];
        float q28 = lrelu(uis[28] + t.x), q29 = lrelu(uis[29] + t.y),
              q30 = lrelu(uis[30] + t.z), q31 = lrelu(uis[31] + t.w);

        // h2 = bm2 + W2^T h1 : 32 named scalar accumulators
        float c0  = b2s[0],  c1  = b2s[1],  c2  = b2s[2],  c3  = b2s[3],
              c4  = b2s[4],  c5  = b2s[5],  c6  = b2s[6],  c7  = b2s[7],
              c8  = b2s[8],  c9  = b2s[9],  c10 = b2s[10], c11 = b2s[11],
              c12 = b2s[12], c13 = b2s[13], c14 = b2s[14], c15 = b2s[15],
              c16 = b2s[16], c17 = b2s[17], c18 = b2s[18], c19 = b2s[19],
              c20 = b2s[20], c21 = b2s[21], c22 = b2s[22], c23 = b2s[23],
              c24 = b2s[24], c25 = b2s[25], c26 = b2s[26], c27 = b2s[27],
              c28 = b2s[28], c29 = b2s[29], c30 = b2s[30], c31 = b2s[31];

        L2STEP(0,  q0);  L2STEP(1,  q1);  L2STEP(2,  q2);  L2STEP(3,  q3);
        L2STEP(4,  q4);  L2STEP(5,  q5);  L2STEP(6,  q6);  L2STEP(7,  q7);
        L2STEP(8,  q8);  L2STEP(9,  q9);  L2STEP(10, q10); L2STEP(11, q11);
        L2STEP(12, q12); L2STEP(13, q13); L2STEP(14, q14); L2STEP(15, q15);
        L2STEP(16, q16); L2STEP(17, q17); L2STEP(18, q18); L2STEP(19, q19);
        L2STEP(20, q20); L2STEP(21, q21); L2STEP(22, q22); L2STEP(23, q23);
        L2STEP(24, q24); L2STEP(25, q25); L2STEP(26, q26); L2STEP(27, q27);
        L2STEP(28, q28); L2STEP(29, q29); L2STEP(30, q30); L2STEP(31, q31);

        // me = tanh(W3 . lrelu(h2) + b3)
        float s = 0.0f;
        S3(0)  S3(1)  S3(2)  S3(3)  S3(4)  S3(5)  S3(6)  S3(7)
        S3(8)  S3(9)  S3(10) S3(11) S3(12) S3(13) S3(14) S3(15)
        S3(16) S3(17) S3(18) S3(19) S3(20) S3(21) S3(22) S3(23)
        S3(24) S3(25) S3(26) S3(27) S3(28) S3(29) S3(30) S3(31)

        float me = tanhf(s + bm3v);
        acc += Arow[j] * me;                 // coalesced A read
    }

    // Block reduction of A-weighted message sum.
    red[tid] = acc;
    __syncthreads();
    #pragma unroll
    for (int s2 = 128; s2 > 0; s2 >>= 1) {
        if (tid < s2) red[tid] += red[tid + s2];
        __syncthreads();
    }

    // Node MLP: x2 = (rho_i, msg_sum) -> 32 -> 32 -> 1 (warp 0, lane = hidden unit)
    if (tid < HH) {
        const float msum = red[0];
        const float rho  = x[bi * 2 + 0];
        const int   l    = tid;

        float h1b = lrelu(rho * Wx1[l] + msum * Wx1[HH + l] + bx1[l]);
        hsh[l] = h1b;
        __syncwarp();

        float h2b = bx2[l];
        #pragma unroll
        for (int k = 0; k < HH; ++k) h2b += Wx2[k * HH + l] * hsh[k];

        float v = lrelu(h2b) * Wx3[l];
        #pragma unroll
        for (int off = 16; off; off >>= 1) v += __shfl_xor_sync(0xffffffffu, v, off);

        if (l == 0) out[bi] = tanhf(v + bx3[0]);
    }
}

// ---------------------------------------------------------------------------
extern "C" void kernel_launch(void* const* d_in, const int* in_sizes, int n_in,
                              void* d_out, int out_size) {
    const float* x   = (const float*)d_in[0];
    const float* A   = (const float*)d_in[1];
    const float* Wm1 = (const float*)d_in[2];
    const float* bm1 = (const float*)d_in[3];
    const float* Wm2 = (const float*)d_in[4];
    const float* bm2 = (const float*)d_in[5];
    const float* Wm3 = (const float*)d_in[6];
    const float* bm3 = (const float*)d_in[7];
    const float* Wx1 = (const float*)d_in[8];
    const float* bx1 = (const float*)d_in[9];
    const float* Wx2 = (const float*)d_in[10];
    const float* bx2 = (const float*)d_in[11];
    const float* Wx3 = (const float*)d_in[12];
    const float* bx3 = (const float*)d_in[13];
    float* out = (float*)d_out;

    precompute_u<<<(BN * HH) / 256, 256>>>(x, Wm1, bm1);
    mpnn_main<<<BN, 256>>>(x, A, Wm2, bm2, Wm3, bm3,
                           Wx1, bx1, Wx2, bx2, Wx3, bx3, out);
}

// round 5
// speedup vs baseline: 1.5161x; 1.5161x over previous
#include <cuda_runtime.h>

#define BB 8
#define NN 1024
#define HH 32
#define BN (BB*NN)

// Scratch: per-node first-layer partials u[n][h] = rho*W1[0][h] + V*W1[1][h] + 0.5*b1[h]
__device__ float g_u[BN * HH];

__device__ __forceinline__ float lrelu(float v) { return fmaxf(v, 0.01f * v); }

// ---------------------------------------------------------------------------
// Kernel 1: per-node layer-1 partials.
// ---------------------------------------------------------------------------
__global__ void precompute_u(const float* __restrict__ x,
                             const float* __restrict__ Wm1,
                             const float* __restrict__ bm1) {
    int idx = blockIdx.x * blockDim.x + threadIdx.x;   // [0, BN*HH)
    int node = idx >> 5;
    int h = idx & 31;
    float rho = x[node * 2 + 0];
    float V   = x[node * 2 + 1];
    g_u[idx] = rho * Wm1[h] + V * Wm1[HH + h] + 0.5f * bm1[h];
}

// Pass A: W2 columns 0..15 (4 LDS.128 + 16 FFMA per k-step)
#define L2A(K, H) do {                                                         \
    float4 wa = W2s[(K)*8+0]; c0  += wa.x*(H); c1  += wa.y*(H); c2  += wa.z*(H); c3  += wa.w*(H); \
    float4 wb = W2s[(K)*8+1]; c4  += wb.x*(H); c5  += wb.y*(H); c6  += wb.z*(H); c7  += wb.w*(H); \
    float4 wc = W2s[(K)*8+2]; c8  += wc.x*(H); c9  += wc.y*(H); c10 += wc.z*(H); c11 += wc.w*(H); \
    float4 wd = W2s[(K)*8+3]; c12 += wd.x*(H); c13 += wd.y*(H); c14 += wd.z*(H); c15 += wd.w*(H); \
} while (0)

// Pass B: W2 columns 16..31
#define L2B(K, H) do {                                                         \
    float4 we = W2s[(K)*8+4]; c16 += we.x*(H); c17 += we.y*(H); c18 += we.z*(H); c19 += we.w*(H); \
    float4 wf = W2s[(K)*8+5]; c20 += wf.x*(H); c21 += wf.y*(H); c22 += wf.z*(H); c23 += wf.w*(H); \
    float4 wg = W2s[(K)*8+6]; c24 += wg.x*(H); c25 += wg.y*(H); c26 += wg.z*(H); c27 += wg.w*(H); \
    float4 wh = W2s[(K)*8+7]; c28 += wh.x*(H); c29 += wh.y*(H); c30 += wh.z*(H); c31 += wh.w*(H); \
} while (0)

#define S3(L) s += lrelu(c##L) * W3s[L];

// ---------------------------------------------------------------------------
// Kernel 2: fused pair-MLP + A-weighted reduction + node MLP.
// One block per (b, i). 256 threads; each thread handles 4 j values.
// __launch_bounds__(256, 2): register budget 128/thread — forbids the
// 32-reg max-occupancy allocation that spilled everything in R3/R4.
// ---------------------------------------------------------------------------
__global__ __launch_bounds__(256, 2) void mpnn_main(
    const float* __restrict__ x,   const float* __restrict__ A,
    const float* __restrict__ Wm2, const float* __restrict__ bm2,
    const float* __restrict__ Wm3, const float* __restrict__ bm3,
    const float* __restrict__ Wx1, const float* __restrict__ bx1,
    const float* __restrict__ Wx2, const float* __restrict__ bx2,
    const float* __restrict__ Wx3, const float* __restrict__ bx3,
    float* __restrict__ out)
{
    __shared__ float4 W2s[HH * 8];     // Wm2 row-major [k][l], 1024 floats
    __shared__ float  W3s[HH];
    __shared__ float  b2s[HH];
    __shared__ float  uis[HH];
    __shared__ float  red[256];
    __shared__ float  hsh[HH];

    const int bi  = blockIdx.x;        // b*N + i
    const int i   = bi & (NN - 1);
    const int tid = threadIdx.x;

    W2s[tid] = reinterpret_cast<const float4*>(Wm2)[tid];  // 256 float4 = 1024 floats
    if (tid < HH) {
        W3s[tid] = Wm3[tid];
        b2s[tid] = bm2[tid];
        uis[tid] = g_u[bi * HH + tid];
    }
    __syncthreads();

    const float* uB   = g_u + (bi & ~(NN - 1)) * HH;  // batch base of u
    const float* Arow = A + (long)i * NN;
    const float  bm3v = bm3[0];

    float acc = 0.0f;

    #pragma unroll 1
    for (int j = tid; j < NN; j += 256) {
        const float4* up = reinterpret_cast<const float4*>(uB + j * HH);

        // h1 = lrelu(u_i + u_j) : 32 named scalars q0..q31
        float4 t;
        t = up[0];
        float q0  = lrelu(uis[0]  + t.x), q1  = lrelu(uis[1]  + t.y),
              q2  = lrelu(uis[2]  + t.z), q3  = lrelu(uis[3]  + t.w);
        t = up[1];
        float q4  = lrelu(uis[4]  + t.x), q5  = lrelu(uis[5]  + t.y),
              q6  = lrelu(uis[6]  + t.z), q7  = lrelu(uis[7]  + t.w);
        t = up[2];
        float q8  = lrelu(uis[8]  + t.x), q9  = lrelu(uis[9]  + t.y),
              q10 = lrelu(uis[10] + t.z), q11 = lrelu(uis[11] + t.w);
        t = up[3];
        float q12 = lrelu(uis[12] + t.x), q13 = lrelu(uis[13] + t.y),
              q14 = lrelu(uis[14] + t.z), q15 = lrelu(uis[15] + t.w);
        t = up[4];
        float q16 = lrelu(uis[16] + t.x), q17 = lrelu(uis[17] + t.y),
              q18 = lrelu(uis[18] + t.z), q19 = lrelu(uis[19] + t.w);
        t = up[5];
        float q20 = lrelu(uis[20] + t.x), q21 = lrelu(uis[21] + t.y),
              q22 = lrelu(uis[22] + t.z), q23 = lrelu(uis[23] + t.w);
        t = up[6];
        float q24 = lrelu(uis[24] + t.x), q25 = lrelu(uis[25] + t.y),
              q26 = lrelu(uis[26] + t.z), q27 = lrelu(uis[27] + t.w);
        t = up[7];
        float q28 = lrelu(uis[28] + t.x), q29 = lrelu(uis[29] + t.y),
              q30 = lrelu(uis[30] + t.z), q31 = lrelu(uis[31] + t.w);

        float s = 0.0f;

        // ---- Pass A: h2[0..15] ----
        {
            float c0  = b2s[0],  c1  = b2s[1],  c2  = b2s[2],  c3  = b2s[3],
                  c4  = b2s[4],  c5  = b2s[5],  c6  = b2s[6],  c7  = b2s[7],
                  c8  = b2s[8],  c9  = b2s[9],  c10 = b2s[10], c11 = b2s[11],
                  c12 = b2s[12], c13 = b2s[13], c14 = b2s[14], c15 = b2s[15];

            L2A(0,  q0);  L2A(1,  q1);  L2A(2,  q2);  L2A(3,  q3);
            L2A(4,  q4);  L2A(5,  q5);  L2A(6,  q6);  L2A(7,  q7);
            L2A(8,  q8);  L2A(9,  q9);  L2A(10, q10); L2A(11, q11);
            L2A(12, q12); L2A(13, q13); L2A(14, q14); L2A(15, q15);
            L2A(16, q16); L2A(17, q17); L2A(18, q18); L2A(19, q19);
            L2A(20, q20); L2A(21, q21); L2A(22, q22); L2A(23, q23);
            L2A(24, q24); L2A(25, q25); L2A(26, q26); L2A(27, q27);
            L2A(28, q28); L2A(29, q29); L2A(30, q30); L2A(31, q31);

            S3(0)  S3(1)  S3(2)  S3(3)  S3(4)  S3(5)  S3(6)  S3(7)
            S3(8)  S3(9)  S3(10) S3(11) S3(12) S3(13) S3(14) S3(15)
        }

        // ---- Pass B: h2[16..31] ----
        {
            float c16 = b2s[16], c17 = b2s[17], c18 = b2s[18], c19 = b2s[19],
                  c20 = b2s[20], c21 = b2s[21], c22 = b2s[22], c23 = b2s[23],
                  c24 = b2s[24], c25 = b2s[25], c26 = b2s[26], c27 = b2s[27],
                  c28 = b2s[28], c29 = b2s[29], c30 = b2s[30], c31 = b2s[31];

            L2B(0,  q0);  L2B(1,  q1);  L2B(2,  q2);  L2B(3,  q3);
            L2B(4,  q4);  L2B(5,  q5);  L2B(6,  q6);  L2B(7,  q7);
            L2B(8,  q8);  L2B(9,  q9);  L2B(10, q10); L2B(11, q11);
            L2B(12, q12); L2B(13, q13); L2B(14, q14); L2B(15, q15);
            L2B(16, q16); L2B(17, q17); L2B(18, q18); L2B(19, q19);
            L2B(20, q20); L2B(21, q21); L2B(22, q22); L2B(23, q23);
            L2B(24, q24); L2B(25, q25); L2B(26, q26); L2B(27, q27);
            L2B(28, q28); L2B(29, q29); L2B(30, q30); L2B(31, q31);

            S3(16) S3(17) S3(18) S3(19) S3(20) S3(21) S3(22) S3(23)
            S3(24) S3(25) S3(26) S3(27) S3(28) S3(29) S3(30) S3(31)
        }

        float me = tanhf(s + bm3v);
        acc += Arow[j] * me;                 // coalesced A read
    }

    // Block reduction of A-weighted message sum.
    red[tid] = acc;
    __syncthreads();
    #pragma unroll
    for (int s2 = 128; s2 > 0; s2 >>= 1) {
        if (tid < s2) red[tid] += red[tid + s2];
        __syncthreads();
    }

    // Node MLP: x2 = (rho_i, msg_sum) -> 32 -> 32 -> 1 (warp 0, lane = hidden unit)
    if (tid < HH) {
        const float msum = red[0];
        const float rho  = x[bi * 2 + 0];
        const int   l    = tid;

        float h1b = lrelu(rho * Wx1[l] + msum * Wx1[HH + l] + bx1[l]);
        hsh[l] = h1b;
        __syncwarp();

        float h2b = bx2[l];
        #pragma unroll
        for (int k = 0; k < HH; ++k) h2b += Wx2[k * HH + l] * hsh[k];

        float v = lrelu(h2b) * Wx3[l];
        #pragma unroll
        for (int off = 16; off; off >>= 1) v += __shfl_xor_sync(0xffffffffu, v, off);

        if (l == 0) out[bi] = tanhf(v + bx3[0]);
    }
}

// ---------------------------------------------------------------------------
extern "C" void kernel_launch(void* const* d_in, const int* in_sizes, int n_in,
                              void* d_out, int out_size) {
    const float* x   = (const float*)d_in[0];
    const float* A   = (const float*)d_in[1];
    const float* Wm1 = (const float*)d_in[2];
    const float* bm1 = (const float*)d_in[3];
    const float* Wm2 = (const float*)d_in[4];
    const float* bm2 = (const float*)d_in[5];
    const float* Wm3 = (const float*)d_in[6];
    const float* bm3 = (const float*)d_in[7];
    const float* Wx1 = (const float*)d_in[8];
    const float* bx1 = (const float*)d_in[9];
    const float* Wx2 = (const float*)d_in[10];
    const float* bx2 = (const float*)d_in[11];
    const float* Wx3 = (const float*)d_in[12];
    const float* bx3 = (const float*)d_in[13];
    float* out = (float*)d_out;

    precompute_u<<<(BN * HH) / 256, 256>>>(x, Wm1, bm1);
    mpnn_main<<<BN, 256>>>(x, A, Wm2, bm2, Wm3, bm3,
                           Wx1, bx1, Wx2, bx2, Wx3, bx3, out);
}

// round 6
// speedup vs baseline: 10.2778x; 6.7790x over previous
#include <cuda_runtime.h>

#define BB 8
#define NN 1024
#define HH 32
#define BN (BB*NN)

// Scratch: per-node first-layer partials u[n][h] = rho*W1[0][h] + V*W1[1][h] + 0.5*b1[h]
__device__ float g_u[BN * HH];

__device__ __forceinline__ float lrelu(float v) { return fmaxf(v, 0.01f * v); }

// ---------------------------------------------------------------------------
// Kernel 1: per-node layer-1 partials.
// ---------------------------------------------------------------------------
__global__ void precompute_u(const float* __restrict__ x,
                             const float* __restrict__ Wm1,
                             const float* __restrict__ bm1) {
    int idx = blockIdx.x * blockDim.x + threadIdx.x;   // [0, BN*HH)
    int node = idx >> 5;
    int h = idx & 31;
    float rho = x[node * 2 + 0];
    float V   = x[node * 2 + 1];
    g_u[idx] = rho * Wm1[h] + V * Wm1[HH + h] + 0.5f * bm1[h];
}

// One layer-2 k-step: broadcast lane k's activation, FMA into lane-resident c.
#define KSTEP(K) c += w##K * __shfl_sync(0xffffffffu, q, K);
#define KSTEP2(K) c2 += w##K * __shfl_sync(0xffffffffu, q2, K);

// ---------------------------------------------------------------------------
// Kernel 2: fused pair-MLP + A-weighted reduction + node MLP.
// One block per (b, i); 8 warps x 128 pairs. Lane = hidden unit.
// The pair's hidden vector is distributed across the warp: NO per-thread
// arrays exist, so local-memory demotion is structurally impossible.
// ---------------------------------------------------------------------------
__global__ __launch_bounds__(256, 2) void mpnn_main(
    const float* __restrict__ x,   const float* __restrict__ A,
    const float* __restrict__ Wm2, const float* __restrict__ bm2,
    const float* __restrict__ Wm3, const float* __restrict__ bm3,
    const float* __restrict__ Wx1, const float* __restrict__ bx1,
    const float* __restrict__ Wx2, const float* __restrict__ bx2,
    const float* __restrict__ Wx3, const float* __restrict__ bx3,
    float* __restrict__ out)
{
    __shared__ float red[256];
    __shared__ float hsh[HH];

    const int bi   = blockIdx.x;       // b*N + i
    const int i    = bi & (NN - 1);
    const int tid  = threadIdx.x;
    const int lane = tid & 31;
    const int wrp  = tid >> 5;         // 0..7

    // Per-lane constants (lane = hidden unit index).
    const float w3l  = Wm3[lane];
    const float b2l  = bm2[lane];
    const float uil  = g_u[bi * HH + lane];
    const float bm3v = bm3[0];

    // W2 column `lane` in 32 loop-invariant named registers (coalesced loads).
    const float w0  = Wm2[ 0*HH + lane], w1  = Wm2[ 1*HH + lane],
                w2  = Wm2[ 2*HH + lane], w3  = Wm2[ 3*HH + lane],
                w4  = Wm2[ 4*HH + lane], w5  = Wm2[ 5*HH + lane],
                w6  = Wm2[ 6*HH + lane], w7  = Wm2[ 7*HH + lane],
                w8  = Wm2[ 8*HH + lane], w9  = Wm2[ 9*HH + lane],
                w10 = Wm2[10*HH + lane], w11 = Wm2[11*HH + lane],
                w12 = Wm2[12*HH + lane], w13 = Wm2[13*HH + lane],
                w14 = Wm2[14*HH + lane], w15 = Wm2[15*HH + lane],
                w16 = Wm2[16*HH + lane], w17 = Wm2[17*HH + lane],
                w18 = Wm2[18*HH + lane], w19 = Wm2[19*HH + lane],
                w20 = Wm2[20*HH + lane], w21 = Wm2[21*HH + lane],
                w22 = Wm2[22*HH + lane], w23 = Wm2[23*HH + lane],
                w24 = Wm2[24*HH + lane], w25 = Wm2[25*HH + lane],
                w26 = Wm2[26*HH + lane], w27 = Wm2[27*HH + lane],
                w28 = Wm2[28*HH + lane], w29 = Wm2[29*HH + lane],
                w30 = Wm2[30*HH + lane], w31 = Wm2[31*HH + lane];

    const float* uB   = g_u + (bi & ~(NN - 1)) * HH;  // batch base of u
    const float* Arow = A + (long)i * NN;

    float acc = 0.0f;

    // Each warp handles 128 contiguous pairs, in 4 batches of 32.
    #pragma unroll 1
    for (int j0 = wrp * 128; j0 < wrp * 128 + 128; j0 += 32) {
        float skeep = 0.0f;
        const float* uj_base = uB + (long)j0 * HH + lane;

        #pragma unroll 2
        for (int jj = 0; jj < 32; jj += 2) {
            // ---- pair j0+jj ----
            {
                float vv = uil + uj_base[jj * HH];          // coalesced LDG
                float q  = lrelu(vv);
                float c  = b2l;
                KSTEP(0)  KSTEP(1)  KSTEP(2)  KSTEP(3)
                KSTEP(4)  KSTEP(5)  KSTEP(6)  KSTEP(7)
                KSTEP(8)  KSTEP(9)  KSTEP(10) KSTEP(11)
                KSTEP(12) KSTEP(13) KSTEP(14) KSTEP(15)
                KSTEP(16) KSTEP(17) KSTEP(18) KSTEP(19)
                KSTEP(20) KSTEP(21) KSTEP(22) KSTEP(23)
                KSTEP(24) KSTEP(25) KSTEP(26) KSTEP(27)
                KSTEP(28) KSTEP(29) KSTEP(30) KSTEP(31)
                float p = lrelu(c) * w3l;
                p += __shfl_xor_sync(0xffffffffu, p, 16);
                p += __shfl_xor_sync(0xffffffffu, p, 8);
                p += __shfl_xor_sync(0xffffffffu, p, 4);
                p += __shfl_xor_sync(0xffffffffu, p, 2);
                p += __shfl_xor_sync(0xffffffffu, p, 1);
                skeep = (lane == jj) ? p : skeep;           // lane jj keeps pair jj's sum
            }
            // ---- pair j0+jj+1 (independent FMA chain for ILP) ----
            {
                float vv2 = uil + uj_base[(jj + 1) * HH];
                float q2  = lrelu(vv2);
                float c2  = b2l;
                KSTEP2(0)  KSTEP2(1)  KSTEP2(2)  KSTEP2(3)
                KSTEP2(4)  KSTEP2(5)  KSTEP2(6)  KSTEP2(7)
                KSTEP2(8)  KSTEP2(9)  KSTEP2(10) KSTEP2(11)
                KSTEP2(12) KSTEP2(13) KSTEP2(14) KSTEP2(15)
                KSTEP2(16) KSTEP2(17) KSTEP2(18) KSTEP2(19)
                KSTEP2(20) KSTEP2(21) KSTEP2(22) KSTEP2(23)
                KSTEP2(24) KSTEP2(25) KSTEP2(26) KSTEP2(27)
                KSTEP2(28) KSTEP2(29) KSTEP2(30) KSTEP2(31)
                float p2 = lrelu(c2) * w3l;
                p2 += __shfl_xor_sync(0xffffffffu, p2, 16);
                p2 += __shfl_xor_sync(0xffffffffu, p2, 8);
                p2 += __shfl_xor_sync(0xffffffffu, p2, 4);
                p2 += __shfl_xor_sync(0xffffffffu, p2, 2);
                p2 += __shfl_xor_sync(0xffffffffu, p2, 1);
                skeep = (lane == jj + 1) ? p2 : skeep;
            }
        }

        // 32 pairs done: lane `t` holds s for pair j0+t. Vectorized tail.
        float me = tanhf(skeep + bm3v);
        acc += Arow[j0 + lane] * me;        // coalesced A read
    }

    // Block reduction of A-weighted message sum.
    red[tid] = acc;
    __syncthreads();
    #pragma unroll
    for (int s2 = 128; s2 > 0; s2 >>= 1) {
        if (tid < s2) red[tid] += red[tid + s2];
        __syncthreads();
    }

    // Node MLP: x2 = (rho_i, msg_sum) -> 32 -> 32 -> 1 (warp 0, lane = hidden unit)
    if (tid < HH) {
        const float msum = red[0];
        const float rho  = x[bi * 2 + 0];
        const int   l    = tid;

        float h1b = lrelu(rho * Wx1[l] + msum * Wx1[HH + l] + bx1[l]);
        hsh[l] = h1b;
        __syncwarp();

        float h2b = bx2[l];
        #pragma unroll
        for (int k = 0; k < HH; ++k) h2b += Wx2[k * HH + l] * hsh[k];

        float v = lrelu(h2b) * Wx3[l];
        #pragma unroll
        for (int off = 16; off; off >>= 1) v += __shfl_xor_sync(0xffffffffu, v, off);

        if (l == 0) out[bi] = tanhf(v + bx3[0]);
    }
}

// ---------------------------------------------------------------------------
extern "C" void kernel_launch(void* const* d_in, const int* in_sizes, int n_in,
                              void* d_out, int out_size) {
    const float* x   = (const float*)d_in[0];
    const float* A   = (const float*)d_in[1];
    const float* Wm1 = (const float*)d_in[2];
    const float* bm1 = (const float*)d_in[3];
    const float* Wm2 = (const float*)d_in[4];
    const float* bm2 = (const float*)d_in[5];
    const float* Wm3 = (const float*)d_in[6];
    const float* bm3 = (const float*)d_in[7];
    const float* Wx1 = (const float*)d_in[8];
    const float* bx1 = (const float*)d_in[9];
    const float* Wx2 = (const float*)d_in[10];
    const float* bx2 = (const float*)d_in[11];
    const float* Wx3 = (const float*)d_in[12];
    const float* bx3 = (const float*)d_in[13];
    float* out = (float*)d_out;

    precompute_u<<<(BN * HH) / 256, 256>>>(x, Wm1, bm1);
    mpnn_main<<<BN, 256>>>(x, A, Wm2, bm2, Wm3, bm3,
                           Wx1, bx1, Wx2, bx2, Wx3, bx3, out);
}

// round 7
// speedup vs baseline: 19.4386x; 1.8913x over previous
#include <cuda_runtime.h>

#define BB 8
#define NN 1024
#define HH 32
#define BN (BB*NN)

typedef unsigned long long u64;

// Scratch: per-node first-layer partials u[n][h] = rho*W1[0][h] + V*W1[1][h] + 0.5*b1[h]
__device__ float g_u[BN * HH];

__device__ __forceinline__ float lrelu(float v) { return fmaxf(v, 0.01f * v); }

__device__ __forceinline__ u64 pack2(float a, float b) {
    u64 r; asm("mov.b64 %0, {%1,%2};" : "=l"(r) : "f"(a), "f"(b)); return r;
}
__device__ __forceinline__ void unpack2(u64 v, float &a, float &b) {
    asm("mov.b64 {%0,%1}, %2;" : "=f"(a), "=f"(b) : "l"(v));
}
// acc.{lo,hi} += a.{lo,hi} * b.{lo,hi}  (packed dual FMA, full fp32 precision)
__device__ __forceinline__ void ffma2(u64 &acc, u64 a, u64 b) {
    asm("fma.rn.f32x2 %0, %1, %2, %0;" : "+l"(acc) : "l"(a), "l"(b));
}
__device__ __forceinline__ u64 add2(u64 a, u64 b) {
    u64 r; asm("add.rn.f32x2 %0, %1, %2;" : "=l"(r) : "l"(a), "l"(b)); return r;
}

// ---------------------------------------------------------------------------
// Kernel 1: per-node layer-1 partials.
// ---------------------------------------------------------------------------
__global__ void precompute_u(const float* __restrict__ x,
                             const float* __restrict__ Wm1,
                             const float* __restrict__ bm1) {
    int idx = blockIdx.x * blockDim.x + threadIdx.x;   // [0, BN*HH)
    int node = idx >> 5;
    int h = idx & 31;
    float rho = x[node * 2 + 0];
    float V   = x[node * 2 + 1];
    g_u[idx] = rho * Wm1[h] + V * Wm1[HH + h] + 0.5f * bm1[h];
}

// W2 column `lane`, k-th element, duplicated into both f32x2 halves.
#define LOADW(K) const u64 W##K = pack2(Wm2[(K)*HH + lane], Wm2[(K)*HH + lane]);

// One duo step: LDS.128 broadcast -> {qA_k,qB_k},{qA_k1,qB_k1}; 2 packed FMAs.
#define DUO(T, KA, KB) { ulonglong2 v = qp[T]; ffma2(ce, W##KA, v.x); ffma2(co, W##KB, v.y); }

// ---------------------------------------------------------------------------
// Kernel 2: fused pair-MLP + A-weighted reduction + node MLP.
// One block per (b,i); 4 warps x 256 pairs, processed in batches of 32.
// Lane = hidden unit; two pairs packed per f32x2 register.
// ---------------------------------------------------------------------------
__global__ __launch_bounds__(128, 4) void mpnn_main(
    const float* __restrict__ x,   const float* __restrict__ A,
    const float* __restrict__ Wm2, const float* __restrict__ bm2,
    const float* __restrict__ Wm3, const float* __restrict__ bm3,
    const float* __restrict__ Wx1, const float* __restrict__ bx1,
    const float* __restrict__ Wx2, const float* __restrict__ bx2,
    const float* __restrict__ Wx3, const float* __restrict__ bx3,
    float* __restrict__ out)
{
    __shared__ float qsh[4][16 * 64];   // per-warp q staging: 16 duos x 64 words (duo-interleaved)
    __shared__ float rsh[4][32 * 33];   // per-warp transpose-reduce tile (pad 33)
    __shared__ float red[128];
    __shared__ float hsh[HH];

    const int bi   = blockIdx.x;        // b*N + i
    const int i    = bi & (NN - 1);
    const int tid  = threadIdx.x;
    const int lane = tid & 31;
    const int wrp  = tid >> 5;          // 0..3

    float* qw = qsh[wrp];
    float* rw = rsh[wrp];

    // Per-lane constants (lane = hidden unit index).
    const float w3l  = Wm3[lane];
    const float uil  = g_u[bi * HH + lane];
    const float bm3v = bm3[0];
    const u64   b2l2 = pack2(bm2[lane], bm2[lane]);

    // W2 column `lane` as 32 loop-invariant packed registers.
    LOADW(0)  LOADW(1)  LOADW(2)  LOADW(3)  LOADW(4)  LOADW(5)  LOADW(6)  LOADW(7)
    LOADW(8)  LOADW(9)  LOADW(10) LOADW(11) LOADW(12) LOADW(13) LOADW(14) LOADW(15)
    LOADW(16) LOADW(17) LOADW(18) LOADW(19) LOADW(20) LOADW(21) LOADW(22) LOADW(23)
    LOADW(24) LOADW(25) LOADW(26) LOADW(27) LOADW(28) LOADW(29) LOADW(30) LOADW(31)

    const float* uB   = g_u + (bi & ~(NN - 1)) * HH;  // batch base of u
    const float* Arow = A + (long)i * NN;

    float acc = 0.0f;

    // Each warp: 256 contiguous pairs, in 8 batches of 32.
    #pragma unroll 1
    for (int j0 = wrp * 256; j0 < wrp * 256 + 256; j0 += 32) {
        const float* ujb = uB + (long)j0 * HH + lane;

        // ---- phase 1: q = lrelu(u_i + u_j) for 32 pairs, stored duo-packed ----
        #pragma unroll
        for (int g = 0; g < 16; ++g) {
            float qa = lrelu(uil + ujb[(2 * g)     * HH]);   // coalesced LDG
            float qb = lrelu(uil + ujb[(2 * g + 1) * HH]);
            *reinterpret_cast<u64*>(&qw[g * 64 + 2 * lane]) = pack2(qa, qb);  // STS.64
        }
        __syncwarp();

        // ---- phase 2: layer 2+3 for each duo (2 pairs packed per register) ----
        #pragma unroll 2
        for (int g = 0; g < 16; ++g) {
            const ulonglong2* qp = reinterpret_cast<const ulonglong2*>(&qw[g * 64]);
            u64 ce = b2l2;                 // even-k chain (carries bias)
            u64 co = pack2(0.0f, 0.0f);    // odd-k chain
            DUO(0,  0,  1)  DUO(1,  2,  3)  DUO(2,  4,  5)  DUO(3,  6,  7)
            DUO(4,  8,  9)  DUO(5,  10, 11) DUO(6,  12, 13) DUO(7,  14, 15)
            DUO(8,  16, 17) DUO(9,  18, 19) DUO(10, 20, 21) DUO(11, 22, 23)
            DUO(12, 24, 25) DUO(13, 26, 27) DUO(14, 28, 29) DUO(15, 30, 31)
            u64 c2 = add2(ce, co);
            float ca, cb; unpack2(c2, ca, cb);
            rw[(2 * g)     * 33 + lane] = lrelu(ca) * w3l;   // conflict-free STS
            rw[(2 * g + 1) * 33 + lane] = lrelu(cb) * w3l;
        }
        __syncwarp();

        // ---- transpose-reduce: lane jj sums row jj (conflict-free, pad 33) ----
        float s0 = 0.0f, s1 = 0.0f, s2 = 0.0f, s3 = 0.0f;
        #pragma unroll
        for (int l = 0; l < 32; l += 4) {
            s0 += rw[lane * 33 + l + 0];
            s1 += rw[lane * 33 + l + 1];
            s2 += rw[lane * 33 + l + 2];
            s3 += rw[lane * 33 + l + 3];
        }
        float me = tanhf((s0 + s1) + (s2 + s3) + bm3v);
        acc += Arow[j0 + lane] * me;                         // coalesced A read
        __syncwarp();
    }

    // Block reduction of A-weighted message sum.
    red[tid] = acc;
    __syncthreads();
    #pragma unroll
    for (int s2 = 64; s2 > 0; s2 >>= 1) {
        if (tid < s2) red[tid] += red[tid + s2];
        __syncthreads();
    }

    // Node MLP: x2 = (rho_i, msg_sum) -> 32 -> 32 -> 1 (warp 0, lane = hidden unit)
    if (tid < HH) {
        const float msum = red[0];
        const float rho  = x[bi * 2 + 0];
        const int   l    = tid;

        float h1b = lrelu(rho * Wx1[l] + msum * Wx1[HH + l] + bx1[l]);
        hsh[l] = h1b;
        __syncwarp();

        float h2b = bx2[l];
        #pragma unroll
        for (int k = 0; k < HH; ++k) h2b += Wx2[k * HH + l] * hsh[k];

        float v = lrelu(h2b) * Wx3[l];
        #pragma unroll
        for (int off = 16; off; off >>= 1) v += __shfl_xor_sync(0xffffffffu, v, off);

        if (l == 0) out[bi] = tanhf(v + bx3[0]);
    }
}

// ---------------------------------------------------------------------------
extern "C" void kernel_launch(void* const* d_in, const int* in_sizes, int n_in,
                              void* d_out, int out_size) {
    const float* x   = (const float*)d_in[0];
    const float* A   = (const float*)d_in[1];
    const float* Wm1 = (const float*)d_in[2];
    const float* bm1 = (const float*)d_in[3];
    const float* Wm2 = (const float*)d_in[4];
    const float* bm2 = (const float*)d_in[5];
    const float* Wm3 = (const float*)d_in[6];
    const float* bm3 = (const float*)d_in[7];
    const float* Wx1 = (const float*)d_in[8];
    const float* bx1 = (const float*)d_in[9];
    const float* Wx2 = (const float*)d_in[10];
    const float* bx2 = (const float*)d_in[11];
    const float* Wx3 = (const float*)d_in[12];
    const float* bx3 = (const float*)d_in[13];
    float* out = (float*)d_out;

    precompute_u<<<(BN * HH) / 256, 256>>>(x, Wm1, bm1);
    mpnn_main<<<BN, 128>>>(x, A, Wm2, bm2, Wm3, bm3,
                           Wx1, bx1, Wx2, bx2, Wx3, bx3, out);
}

// round 8
// speedup vs baseline: 34.7624x; 1.7883x over previous
#include <cuda_runtime.h>

#define BB 8
#define NN 1024
#define HH 32
#define BN (BB*NN)
#define NT 32                          // tile edge
#define NTILES (NN/NT)                 // 32
#define NPAIRT (NTILES*(NTILES+1)/2)   // 528 tile-pairs (ti<=tj)

typedef unsigned long long u64;

// Scratch
__device__ float g_u[BN * HH];                    // per-node layer-1 partials
__device__ float g_part[BB * NTILES * NN];        // [b][other_tile][node] partial msg sums

__device__ __forceinline__ float lrelu(float v) { return fmaxf(v, 0.01f * v); }

__device__ __forceinline__ u64 pack2(float a, float b) {
    u64 r; asm("mov.b64 %0, {%1,%2};" : "=l"(r) : "f"(a), "f"(b)); return r;
}
__device__ __forceinline__ void unpack2(u64 v, float &a, float &b) {
    asm("mov.b64 {%0,%1}, %2;" : "=f"(a), "=f"(b) : "l"(v));
}
__device__ __forceinline__ void ffma2(u64 &acc, u64 a, u64 b) {
    asm("fma.rn.f32x2 %0, %1, %2, %0;" : "+l"(acc) : "l"(a), "l"(b));
}
__device__ __forceinline__ u64 add2(u64 a, u64 b) {
    u64 r; asm("add.rn.f32x2 %0, %1, %2;" : "=l"(r) : "l"(a), "l"(b)); return r;
}

// ---------------------------------------------------------------------------
// Kernel 1: per-node layer-1 partials u[n][h] = rho*W1[0][h] + V*W1[1][h] + b1[h]/2
// ---------------------------------------------------------------------------
__global__ void precompute_u(const float* __restrict__ x,
                             const float* __restrict__ Wm1,
                             const float* __restrict__ bm1) {
    int idx = blockIdx.x * blockDim.x + threadIdx.x;   // [0, BN*HH)
    int node = idx >> 5;
    int h = idx & 31;
    float rho = x[node * 2 + 0];
    float V   = x[node * 2 + 1];
    g_u[idx] = rho * Wm1[h] + V * Wm1[HH + h] + 0.5f * bm1[h];
}

// W2 packed over adjacent k: Wd{g} = {W2[2g][lane], W2[2g+1][lane]}
#define LOADW(G) const u64 Wd##G = pack2(Wm2[(2*(G))*HH + lane], Wm2[(2*(G)+1)*HH + lane]);

// One step for two concurrent pairs: LDS.128 {q4k..q4k+3} per pair, 2 packed FMAs each.
#define PSTEP(T, WA, WB)                                   \
    va = qpa[T]; ffma2(a0, WA, va.x); ffma2(a1, WB, va.y); \
    vb = qpb[T]; ffma2(b0, WA, vb.x); ffma2(b1, WB, vb.y);

// ---------------------------------------------------------------------------
// Kernel 2: symmetric tiled pair-MLP.
// Block = (b, tile-pair ti<=tj). Off-diag tiles credit BOTH (i,j) and (j,i).
// 4 warps; warp w handles i-rows {w, w+4, ..., w+28}; lane = hidden unit.
// ---------------------------------------------------------------------------
__global__ __launch_bounds__(128, 4) void mpnn_pairs(
    const float* __restrict__ A,
    const float* __restrict__ Wm2, const float* __restrict__ bm2,
    const float* __restrict__ Wm3, const float* __restrict__ bm3)
{
    __shared__ float uti[NT * HH];      // u_i tile [r][h]
    __shared__ float utj[NT * HH];      // u_j tile [jj][h]
    __shared__ float acs[NT * 33];      // A[j0+jj][i0+ii], pad 33
    __shared__ float qsh[4][NT * HH];   // per-warp q staging [jj][k]
    __shared__ float rsh[4][NT * 33];   // per-warp p staging [jj][l], pad 33
    __shared__ float csh[4][NT];        // per-warp col accumulators

    const int blk = blockIdx.x;
    const int b   = blk / NPAIRT;
    int tt = blk % NPAIRT;
    int ti = 0;
    while (tt >= NTILES - ti) { tt -= NTILES - ti; ++ti; }
    const int tj = ti + tt;
    const bool diag = (ti == tj);

    const int tid  = threadIdx.x;
    const int lane = tid & 31;
    const int wrp  = tid >> 5;
    const int i0   = ti * NT;
    const int j0   = tj * NT;

    // Stage u tiles (coalesced) and A-column tile.
    const float* ub = g_u + (size_t)b * NN * HH;
    #pragma unroll
    for (int idx = tid; idx < NT * HH; idx += 128) {
        uti[idx] = ub[i0 * HH + idx];
        utj[idx] = ub[j0 * HH + idx];
    }
    if (!diag) {
        #pragma unroll
        for (int idx = tid; idx < NT * NT; idx += 128) {
            int jj = idx >> 5, ii = idx & 31;
            acs[jj * 33 + ii] = A[(size_t)(j0 + jj) * NN + i0 + ii];
        }
    }
    __syncthreads();

    // Per-lane constants (lane = hidden unit).
    const float w3l  = Wm3[lane];
    const float bm3v = bm3[0];
    const u64   binit = pack2(bm2[lane], 0.0f);
    const u64   z2    = pack2(0.0f, 0.0f);

    LOADW(0)  LOADW(1)  LOADW(2)  LOADW(3)
    LOADW(4)  LOADW(5)  LOADW(6)  LOADW(7)
    LOADW(8)  LOADW(9)  LOADW(10) LOADW(11)
    LOADW(12) LOADW(13) LOADW(14) LOADW(15)

    float* qw = qsh[wrp];
    float* rw = rsh[wrp];
    float colacc = 0.0f;

    #pragma unroll 1
    for (int rr = 0; rr < 8; ++rr) {
        const int r = (rr << 2) + wrp;

        // ---- phase 1: q[jj][k] = lrelu(u_i[r][k] + u_j[jj][k]) (lane = k) ----
        const float uil = uti[r * HH + lane];
        #pragma unroll 4
        for (int jj = 0; jj < NT; ++jj)
            qw[jj * HH + lane] = lrelu(uil + utj[jj * HH + lane]);
        __syncwarp();

        // ---- phase 2: layer 2+3 per pair, two pairs in flight ----
        #pragma unroll 1
        for (int jj = 0; jj < NT; jj += 2) {
            const ulonglong2* qpa = reinterpret_cast<const ulonglong2*>(qw + jj * HH);
            const ulonglong2* qpb = reinterpret_cast<const ulonglong2*>(qw + jj * HH + HH);
            u64 a0 = binit, a1 = z2, b0 = binit, b1 = z2;
            ulonglong2 va, vb;
            PSTEP(0, Wd0,  Wd1)  PSTEP(1, Wd2,  Wd3)
            PSTEP(2, Wd4,  Wd5)  PSTEP(3, Wd6,  Wd7)
            PSTEP(4, Wd8,  Wd9)  PSTEP(5, Wd10, Wd11)
            PSTEP(6, Wd12, Wd13) PSTEP(7, Wd14, Wd15)
            u64 sa = add2(a0, a1), sb = add2(b0, b1);
            float xa, ya, xb, yb;
            unpack2(sa, xa, ya); unpack2(sb, xb, yb);
            rw[jj * 33 + lane]       = lrelu(xa + ya) * w3l;
            rw[(jj + 1) * 33 + lane] = lrelu(xb + yb) * w3l;
        }
        __syncwarp();

        // ---- transpose-reduce: lane sums row `lane` (pad-33, conflict-free) ----
        float s0 = 0.0f, s1 = 0.0f, s2 = 0.0f, s3 = 0.0f;
        #pragma unroll
        for (int l = 0; l < 32; l += 4) {
            s0 += rw[lane * 33 + l + 0];
            s1 += rw[lane * 33 + l + 1];
            s2 += rw[lane * 33 + l + 2];
            s3 += rw[lane * 33 + l + 3];
        }
        const float me = tanhf((s0 + s1) + (s2 + s3) + bm3v);  // pair (i0+r, j0+lane)

        // ---- row credit: sum_j A[i][j]*me -> slot ot=tj, node i0+r ----
        float trow = A[(size_t)(i0 + r) * NN + j0 + lane] * me;  // coalesced LDG
        trow += __shfl_xor_sync(0xffffffffu, trow, 16);
        trow += __shfl_xor_sync(0xffffffffu, trow, 8);
        trow += __shfl_xor_sync(0xffffffffu, trow, 4);
        trow += __shfl_xor_sync(0xffffffffu, trow, 2);
        trow += __shfl_xor_sync(0xffffffffu, trow, 1);
        if (lane == 0)
            g_part[(size_t)(b * NTILES + tj) * NN + i0 + r] = trow;

        // ---- col credit: acc_j += A[j][i]*me (off-diag only) ----
        if (!diag)
            colacc += acs[lane * 33 + r] * me;   // conflict-free (stride 33)

        __syncwarp();   // protect qw/rw reuse in next row
    }

    if (!diag) {
        csh[wrp][lane] = colacc;
        __syncthreads();
        if (wrp == 0) {
            float cv = csh[0][lane] + csh[1][lane] + csh[2][lane] + csh[3][lane];
            g_part[(size_t)(b * NTILES + ti) * NN + j0 + lane] = cv;
        }
    }
}

// ---------------------------------------------------------------------------
// Kernel 3: finalize — sum 32 partials per node, run node MLP.
// One warp per node; lane = hidden unit.
// ---------------------------------------------------------------------------
__global__ __launch_bounds__(128) void mpnn_finalize(
    const float* __restrict__ x,
    const float* __restrict__ Wx1, const float* __restrict__ bx1,
    const float* __restrict__ Wx2, const float* __restrict__ bx2,
    const float* __restrict__ Wx3, const float* __restrict__ bx3,
    float* __restrict__ out)
{
    __shared__ float hsh[4][HH];
    const int lane = threadIdx.x & 31;
    const int wrp  = threadIdx.x >> 5;
    const int node = blockIdx.x * 4 + wrp;          // [0, BN)
    const int b    = node >> 10;
    const int i    = node & (NN - 1);

    // lane l reads partial from other_tile = l; butterfly-sum.
    float ps = g_part[(size_t)(b * NTILES + lane) * NN + i];
    #pragma unroll
    for (int off = 16; off; off >>= 1) ps += __shfl_xor_sync(0xffffffffu, ps, off);
    const float msum = ps;

    const float rho = x[node * 2 + 0];
    float h1b = lrelu(rho * Wx1[lane] + msum * Wx1[HH + lane] + bx1[lane]);
    hsh[wrp][lane] = h1b;
    __syncwarp();

    float h2b = bx2[lane];
    #pragma unroll
    for (int k = 0; k < HH; ++k) h2b += Wx2[k * HH + lane] * hsh[wrp][k];

    float v = lrelu(h2b) * Wx3[lane];
    #pragma unroll
    for (int off = 16; off; off >>= 1) v += __shfl_xor_sync(0xffffffffu, v, off);

    if (lane == 0) out[node] = tanhf(v + bx3[0]);
}

// ---------------------------------------------------------------------------
extern "C" void kernel_launch(void* const* d_in, const int* in_sizes, int n_in,
                              void* d_out, int out_size) {
    const float* x   = (const float*)d_in[0];
    const float* A   = (const float*)d_in[1];
    const float* Wm1 = (const float*)d_in[2];
    const float* bm1 = (const float*)d_in[3];
    const float* Wm2 = (const float*)d_in[4];
    const float* bm2 = (const float*)d_in[5];
    const float* Wm3 = (const float*)d_in[6];
    const float* bm3 = (const float*)d_in[7];
    const float* Wx1 = (const float*)d_in[8];
    const float* bx1 = (const float*)d_in[9];
    const float* Wx2 = (const float*)d_in[10];
    const float* bx2 = (const float*)d_in[11];
    const float* Wx3 = (const float*)d_in[12];
    const float* bx3 = (const float*)d_in[13];
    float* out = (float*)d_out;

    precompute_u<<<(BN * HH) / 256, 256>>>(x, Wm1, bm1);
    mpnn_pairs<<<BB * NPAIRT, 128>>>(A, Wm2, bm2, Wm3, bm3);
    mpnn_finalize<<<BN / 4, 128>>>(x, Wx1, bx1, Wx2, bx2, Wx3, bx3, out);
}

// round 10
// speedup vs baseline: 35.4271x; 1.0191x over previous
#include <cuda_runtime.h>

#define BB 8
#define NN 1024
#define HH 32
#define BN (BB*NN)
#define NT 32                          // tile edge
#define NTILES (NN/NT)                 // 32
#define NPAIRT (NTILES*(NTILES+1)/2)   // 528 tile-pairs (ti<=tj)

typedef unsigned long long u64;

// Scratch
__device__ float g_u[BN * HH];                    // per-node layer-1 partials
__device__ float g_part[BB * NTILES * NN];        // [b][other_tile][node] partial msg sums

__device__ __forceinline__ float lrelu(float v) { return fmaxf(v, 0.01f * v); }

__device__ __forceinline__ u64 pack2(float a, float b) {
    u64 r; asm("mov.b64 %0, {%1,%2};" : "=l"(r) : "f"(a), "f"(b)); return r;
}
__device__ __forceinline__ void unpack2(u64 v, float &a, float &b) {
    asm("mov.b64 {%0,%1}, %2;" : "=f"(a), "=f"(b) : "l"(v));
}
__device__ __forceinline__ void ffma2(u64 &acc, u64 a, u64 b) {
    asm("fma.rn.f32x2 %0, %1, %2, %0;" : "+l"(acc) : "l"(a), "l"(b));
}
__device__ __forceinline__ u64 add2(u64 a, u64 b) {
    u64 r; asm("add.rn.f32x2 %0, %1, %2;" : "=l"(r) : "l"(a), "l"(b)); return r;
}

// ---------------------------------------------------------------------------
// Kernel 1: per-node layer-1 partials u[n][h] = rho*W1[0][h] + V*W1[1][h] + b1[h]/2
// ---------------------------------------------------------------------------
__global__ void precompute_u(const float* __restrict__ x,
                             const float* __restrict__ Wm1,
                             const float* __restrict__ bm1) {
    int idx = blockIdx.x * blockDim.x + threadIdx.x;   // [0, BN*HH)
    int node = idx >> 5;
    int h = idx & 31;
    float rho = x[node * 2 + 0];
    float V   = x[node * 2 + 1];
    g_u[idx] = rho * Wm1[h] + V * Wm1[HH + h] + 0.5f * bm1[h];
}

// W2 packed over adjacent k: Wd{g} = {W2[2g][lane], W2[2g+1][lane]}
#define LOADW(G) const u64 Wd##G = pack2(Wm2[(2*(G))*HH + lane], Wm2[(2*(G)+1)*HH + lane]);

// One step for two concurrent pairs: LDS.128 {q4k..q4k+3} per pair, 2 packed FMAs each.
#define PSTEP(T, WA, WB)                                   \
    va = qpa[T]; ffma2(a0, WA, va.x); ffma2(a1, WB, va.y); \
    vb = qpb[T]; ffma2(b0, WA, vb.x); ffma2(b1, WB, vb.y);

// ---------------------------------------------------------------------------
// Kernel 2: symmetric tiled pair-MLP.
// Block = (b, tile-pair ti<=tj). Off-diag tiles credit BOTH (i,j) and (j,i).
// 4 warps; warp w handles i-rows {w, w+4, ..., w+28}; lane = hidden unit.
// ---------------------------------------------------------------------------
__global__ __launch_bounds__(128, 5) void mpnn_pairs(
    const float* __restrict__ A,
    const float* __restrict__ Wm2, const float* __restrict__ bm2,
    const float* __restrict__ Wm3, const float* __restrict__ bm3)
{
    __shared__ __align__(16) float utj[NT * HH];     // u_j tile [jj][h]
    __shared__ __align__(16) float qsh[4][NT * HH];  // per-warp q staging [jj][k]
    __shared__ float rsh[4][NT * 33];                // per-warp p tile (pad 33)
    __shared__ float acs[NT * 33];                   // A[j0+jj][i0+ii], pad 33
    __shared__ float csh[4][NT];                     // per-warp col accumulators

    const int blk = blockIdx.x;
    const int b   = blk / NPAIRT;
    int tt = blk % NPAIRT;
    int ti = 0;
    while (tt >= NTILES - ti) { tt -= NTILES - ti; ++ti; }
    const int tj = ti + tt;
    const bool diag = (ti == tj);

    const int tid  = threadIdx.x;
    const int lane = tid & 31;
    const int wrp  = tid >> 5;
    const int i0   = ti * NT;
    const int j0   = tj * NT;

    // Stage u_j tile (coalesced) and A-column tile.
    const float* ub = g_u + (size_t)b * NN * HH;
    #pragma unroll
    for (int idx = tid; idx < NT * HH; idx += 128)
        utj[idx] = ub[j0 * HH + idx];
    if (!diag) {
        #pragma unroll
        for (int idx = tid; idx < NT * NT; idx += 128) {
            int jj = idx >> 5, ii = idx & 31;
            acs[jj * 33 + ii] = A[(size_t)(j0 + jj) * NN + i0 + ii];
        }
    }
    __syncthreads();

    // Per-lane constants (lane = hidden unit).
    const float w3l  = Wm3[lane];
    const float bm3v = bm3[0];
    const u64   binit = pack2(bm2[lane], 0.0f);
    const u64   z2    = pack2(0.0f, 0.0f);

    LOADW(0)  LOADW(1)  LOADW(2)  LOADW(3)
    LOADW(4)  LOADW(5)  LOADW(6)  LOADW(7)
    LOADW(8)  LOADW(9)  LOADW(10) LOADW(11)
    LOADW(12) LOADW(13) LOADW(14) LOADW(15)

    float* qw = qsh[wrp];
    float* rw = rsh[wrp];
    float colacc = 0.0f;

    #pragma unroll 1
    for (int rr = 0; rr < 8; ++rr) {
        const int r = (rr << 2) + wrp;

        // Prefetch row-credit A value and u_i row (both coalesced LDG).
        const float aval = A[(size_t)(i0 + r) * NN + j0 + lane];
        const float uil  = ub[(size_t)(i0 + r) * HH + lane];

        // ---- phase 1: q[jj][k] = lrelu(u_i[r][k] + u_j[jj][k]) (lane = k) ----
        #pragma unroll 4
        for (int jj = 0; jj < NT; ++jj)
            qw[jj * HH + lane] = lrelu(uil + utj[jj * HH + lane]);
        __syncwarp();

        // ---- phase 2: layer 2+3 per pair, two pairs in flight ----
        #pragma unroll 1
        for (int jj = 0; jj < NT; jj += 2) {
            const ulonglong2* qpa = reinterpret_cast<const ulonglong2*>(qw + jj * HH);
            const ulonglong2* qpb = reinterpret_cast<const ulonglong2*>(qw + jj * HH + HH);
            u64 a0 = binit, a1 = z2, b0 = binit, b1 = z2;
            ulonglong2 va, vb;
            PSTEP(0, Wd0,  Wd1)  PSTEP(1, Wd2,  Wd3)
            PSTEP(2, Wd4,  Wd5)  PSTEP(3, Wd6,  Wd7)
            PSTEP(4, Wd8,  Wd9)  PSTEP(5, Wd10, Wd11)
            PSTEP(6, Wd12, Wd13) PSTEP(7, Wd14, Wd15)
            u64 sa = add2(a0, a1), sb = add2(b0, b1);
            float xa, ya, xb, yb;
            unpack2(sa, xa, ya); unpack2(sb, xb, yb);
            rw[jj * 33 + lane]       = lrelu(xa + ya) * w3l;
            rw[(jj + 1) * 33 + lane] = lrelu(xb + yb) * w3l;
        }
        __syncwarp();

        // ---- transpose-reduce: lane sums row `lane` (pad-33, conflict-free) ----
        float s0 = 0.0f, s1 = 0.0f, s2 = 0.0f, s3 = 0.0f;
        #pragma unroll
        for (int l = 0; l < 32; l += 4) {
            s0 += rw[lane * 33 + l + 0];
            s1 += rw[lane * 33 + l + 1];
            s2 += rw[lane * 33 + l + 2];
            s3 += rw[lane * 33 + l + 3];
        }
        const float me = tanhf((s0 + s1) + (s2 + s3) + bm3v);  // pair (i0+r, j0+lane)

        // ---- row credit: sum_j A[i][j]*me -> slot ot=tj, node i0+r ----
        float trow = aval * me;
        trow += __shfl_xor_sync(0xffffffffu, trow, 16);
        trow += __shfl_xor_sync(0xffffffffu, trow, 8);
        trow += __shfl_xor_sync(0xffffffffu, trow, 4);
        trow += __shfl_xor_sync(0xffffffffu, trow, 2);
        trow += __shfl_xor_sync(0xffffffffu, trow, 1);
        if (lane == 0)
            g_part[(size_t)(b * NTILES + tj) * NN + i0 + r] = trow;

        // ---- col credit: acc_j += A[j][i]*me (off-diag only) ----
        if (!diag)
            colacc += acs[lane * 33 + r] * me;   // conflict-free (stride 33)

        __syncwarp();   // protect qw/rw reuse in next row
    }

    if (!diag) {
        csh[wrp][lane] = colacc;
        __syncthreads();
        if (wrp == 0) {
            float cv = csh[0][lane] + csh[1][lane] + csh[2][lane] + csh[3][lane];
            g_part[(size_t)(b * NTILES + ti) * NN + j0 + lane] = cv;
        }
    }
}

// ---------------------------------------------------------------------------
// Kernel 3: finalize — sum 32 partials per node, run node MLP.
// One warp per node; lane = hidden unit.
// ---------------------------------------------------------------------------
__global__ __launch_bounds__(128) void mpnn_finalize(
    const float* __restrict__ x,
    const float* __restrict__ Wx1, const float* __restrict__ bx1,
    const float* __restrict__ Wx2, const float* __restrict__ bx2,
    const float* __restrict__ Wx3, const float* __restrict__ bx3,
    float* __restrict__ out)
{
    __shared__ float hsh[4][HH];
    const int lane = threadIdx.x & 31;
    const int wrp  = threadIdx.x >> 5;
    const int node = blockIdx.x * 4 + wrp;          // [0, BN)
    const int b    = node >> 10;
    const int i    = node & (NN - 1);

    // lane l reads partial from other_tile = l; butterfly-sum.
    float ps = g_part[(size_t)(b * NTILES + lane) * NN + i];
    #pragma unroll
    for (int off = 16; off; off >>= 1) ps += __shfl_xor_sync(0xffffffffu, ps, off);
    const float msum = ps;

    const float rho = x[node * 2 + 0];
    float h1b = lrelu(rho * Wx1[lane] + msum * Wx1[HH + lane] + bx1[lane]);
    hsh[wrp][lane] = h1b;
    __syncwarp();

    float h2b = bx2[lane];
    #pragma unroll
    for (int k = 0; k < HH; ++k) h2b += Wx2[k * HH + lane] * hsh[wrp][k];

    float v = lrelu(h2b) * Wx3[lane];
    #pragma unroll
    for (int off = 16; off; off >>= 1) v += __shfl_xor_sync(0xffffffffu, v, off);

    if (lane == 0) out[node] = tanhf(v + bx3[0]);
}

// ---------------------------------------------------------------------------
extern "C" void kernel_launch(void* const* d_in, const int* in_sizes, int n_in,
                              void* d_out, int out_size) {
    const float* x   = (const float*)d_in[0];
    const float* A   = (const float*)d_in[1];
    const float* Wm1 = (const float*)d_in[2];
    const float* bm1 = (const float*)d_in[3];
    const float* Wm2 = (const float*)d_in[4];
    const float* bm2 = (const float*)d_in[5];
    const float* Wm3 = (const float*)d_in[6];
    const float* bm3 = (const float*)d_in[7];
    const float* Wx1 = (const float*)d_in[8];
    const float* bx1 = (const float*)d_in[9];
    const float* Wx2 = (const float*)d_in[10];
    const float* bx2 = (const float*)d_in[11];
    const float* Wx3 = (const float*)d_in[12];
    const float* bx3 = (const float*)d_in[13];
    float* out = (float*)d_out;

    precompute_u<<<(BN * HH) / 256, 256>>>(x, Wm1, bm1);
    mpnn_pairs<<<BB * NPAIRT, 128>>>(A, Wm2, bm2, Wm3, bm3);
    mpnn_finalize<<<BN / 4, 128>>>(x, Wx1, bx1, Wx2, bx2, Wx3, bx3, out);
}

// round 15
// speedup vs baseline: 61.0630x; 1.7236x over previous
#include <cuda_runtime.h>
#include <cstdint>

#define BB 8
#define NN 1024
#define HH 32
#define BN (BB*NN)
#define NT 32
#define NTILES 32                      // NN/NT
#define NPAIRT 528                     // NTILES*(NTILES+1)/2

#define QPAD 36                        // q_s row stride: (4*row+col)%32 distinct for frag loads
#define WPAD 40                        // W_s row stride: (8*row+col)%32 distinct for frag loads

// Scratch
__device__ float g_u[BN * HH];                 // per-node layer-1 partials
__device__ float g_part[BB * NTILES * NN];     // [b][other_tile][node] partials

__device__ __forceinline__ float lrelu(float v) { return fmaxf(v, 0.01f * v); }
// tf32 = f32 with mantissa truncated to 10 bits: mask bits [12:0]
__device__ __forceinline__ uint32_t tf32_hi(float v) { return __float_as_uint(v) & 0xFFFFE000u; }

// D += A(tf32) * B(tf32), m16n8k8, fp32 accumulate (baseline sm_80+ HMMA — no 'a' gating)
#define MMA_TF32(d0,d1,d2,d3, a0,a1,a2,a3, b0,b1)                                   \
    asm volatile("mma.sync.aligned.m16n8k8.row.col.f32.tf32.tf32.f32 "              \
                 "{%0,%1,%2,%3}, {%4,%5,%6,%7}, {%8,%9}, {%0,%1,%2,%3};"            \
                 : "+f"(d0), "+f"(d1), "+f"(d2), "+f"(d3)                           \
                 : "r"(a0), "r"(a1), "r"(a2), "r"(a3), "r"(b0), "r"(b1))

// ---------------------------------------------------------------------------
// Kernel 1: per-node layer-1 partials u[n][h] = rho*W1[0][h] + V*W1[1][h] + b1[h]/2
// ---------------------------------------------------------------------------
__global__ void precompute_u(const float* __restrict__ x,
                             const float* __restrict__ Wm1,
                             const float* __restrict__ bm1) {
    int idx = blockIdx.x * blockDim.x + threadIdx.x;
    int node = idx >> 5;
    int h = idx & 31;
    float rho = x[node * 2 + 0];
    float V   = x[node * 2 + 1];
    g_u[idx] = rho * Wm1[h] + V * Wm1[HH + h] + 0.5f * bm1[h];
}

// ---------------------------------------------------------------------------
// Kernel 2: symmetric tiled pair-MLP; layer 2 on tensor pipe (tf32 HMMA x3).
// Block = (b, tile-pair ti<=tj); 4 warps; warp w does rows r = c*4+w.
// Per warp-chunk: M=32 pairs x N=32 l x K=32 GEMM = 2Mx4Nx4K m16n8k8 MMAs.
// ---------------------------------------------------------------------------
__global__ __launch_bounds__(128, 4) void mpnn_pairs(
    const float* __restrict__ A,
    const float* __restrict__ Wm2, const float* __restrict__ bm2,
    const float* __restrict__ Wm3, const float* __restrict__ bm3)
{
    __shared__ float    qs[4][NT * QPAD];   // per-warp q staging [pair][k]
    __shared__ uint32_t whi[NT * WPAD];     // W2 hi (tf32 bits) [k][l]
    __shared__ uint32_t wlo[NT * WPAD];     // W2 lo (tf32 bits) [k][l]
    __shared__ float    b2s[HH], w3s[HH];
    __shared__ float    csh[4][NT];

    const int blk = blockIdx.x;
    const int b   = blk / NPAIRT;
    int tt = blk % NPAIRT;
    int ti = 0;
    while (tt >= NTILES - ti) { tt -= NTILES - ti; ++ti; }
    const int tj = ti + tt;
    const bool diag = (ti == tj);

    const int tid  = threadIdx.x;
    const int lane = tid & 31;
    const int wrp  = tid >> 5;
    const int grp  = lane >> 2;        // 0..7
    const int tg   = lane & 3;         // 0..3
    const int i0   = ti * NT;
    const int j0   = tj * NT;

    // ---- stage W2 as tf32 hi/lo ----
    #pragma unroll 1
    for (int idx = tid; idx < HH * HH; idx += 128) {
        int k = idx >> 5, l = idx & 31;
        float w = Wm2[idx];
        uint32_t h = tf32_hi(w);
        float lof  = w - __uint_as_float(h);
        whi[k * WPAD + l] = h;
        wlo[k * WPAD + l] = tf32_hi(lof);
    }
    if (tid < HH) { b2s[tid] = bm2[tid]; w3s[tid] = Wm3[tid]; }
    __syncthreads();

    const float* ub = g_u + (size_t)b * NN * HH;
    const float bm3v = bm3[0];
    float* qw = qs[wrp];
    float colacc[4] = {0.f, 0.f, 0.f, 0.f};

    #pragma unroll 1
    for (int c = 0; c < 8; ++c) {
        const int r = (c << 2) + wrp;

        // ---- phase 1: q[jj][k] = lrelu(u_i[r][k] + u_j[jj][k]); lane = k ----
        const float uir = ub[(size_t)(i0 + r) * HH + lane];
        #pragma unroll
        for (int jj = 0; jj < NT; ++jj) {
            float uj = ub[(size_t)(j0 + jj) * HH + lane];      // coalesced, L1-resident
            qw[jj * QPAD + lane] = lrelu(uir + uj);             // conflict-free (pad 36)
        }
        __syncwarp();

        // ---- phase 2: tf32x3 HMMA: D[pair][l] = Q Qlo x Whi/Wlo ----
        float d[2][4][4];
        #pragma unroll
        for (int m = 0; m < 2; ++m)
            #pragma unroll
            for (int n = 0; n < 4; ++n)
                #pragma unroll
                for (int e = 0; e < 4; ++e) d[m][n][e] = 0.f;

        #pragma unroll
        for (int kt = 0; kt < 4; ++kt) {
            uint32_t ah[2][4], al[2][4];
            #pragma unroll
            for (int m = 0; m < 2; ++m) {
                float f0 = qw[(16*m + grp)     * QPAD + 8*kt + tg];
                float f1 = qw[(16*m + grp + 8) * QPAD + 8*kt + tg];
                float f2 = qw[(16*m + grp)     * QPAD + 8*kt + tg + 4];
                float f3 = qw[(16*m + grp + 8) * QPAD + 8*kt + tg + 4];
                ah[m][0] = tf32_hi(f0); al[m][0] = tf32_hi(f0 - __uint_as_float(ah[m][0]));
                ah[m][1] = tf32_hi(f1); al[m][1] = tf32_hi(f1 - __uint_as_float(ah[m][1]));
                ah[m][2] = tf32_hi(f2); al[m][2] = tf32_hi(f2 - __uint_as_float(ah[m][2]));
                ah[m][3] = tf32_hi(f3); al[m][3] = tf32_hi(f3 - __uint_as_float(ah[m][3]));
            }
            #pragma unroll
            for (int n = 0; n < 4; ++n) {
                uint32_t bh0 = whi[(8*kt + tg)     * WPAD + 8*n + grp];
                uint32_t bh1 = whi[(8*kt + tg + 4) * WPAD + 8*n + grp];
                uint32_t bl0 = wlo[(8*kt + tg)     * WPAD + 8*n + grp];
                uint32_t bl1 = wlo[(8*kt + tg + 4) * WPAD + 8*n + grp];
                #pragma unroll
                for (int m = 0; m < 2; ++m) {
                    MMA_TF32(d[m][n][0], d[m][n][1], d[m][n][2], d[m][n][3],
                             ah[m][0], ah[m][1], ah[m][2], ah[m][3], bh0, bh1);
                    MMA_TF32(d[m][n][0], d[m][n][1], d[m][n][2], d[m][n][3],
                             ah[m][0], ah[m][1], ah[m][2], ah[m][3], bl0, bl1);
                    MMA_TF32(d[m][n][0], d[m][n][1], d[m][n][2], d[m][n][3],
                             al[m][0], al[m][1], al[m][2], al[m][3], bh0, bh1);
                }
            }
        }

        // ---- epilogue: thread owns pairs jj = grp + 8t; cols l = 8n + 2tg(+1) ----
        float me[4];
        #pragma unroll
        for (int t = 0; t < 4; ++t) {
            const int m  = t >> 1;
            const int o0 = (t & 1) << 1;           // 0 (row grp) or 2 (row grp+8)
            float s = 0.f;
            #pragma unroll
            for (int n = 0; n < 4; ++n) {
                int l0 = 8*n + 2*tg;
                s += lrelu(d[m][n][o0]     + b2s[l0])     * w3s[l0];
                s += lrelu(d[m][n][o0 + 1] + b2s[l0 + 1]) * w3s[l0 + 1];
            }
            s += __shfl_xor_sync(0xffffffffu, s, 1);   // sum over tg (4-lane group)
            s += __shfl_xor_sync(0xffffffffu, s, 2);
            me[t] = tanhf(s + bm3v);
        }

        // ---- row credit: sum_jj A[i0+r][j0+jj]*me[jj] ----
        float tr = 0.f;
        if (tg == 0) {
            #pragma unroll
            for (int t = 0; t < 4; ++t)
                tr += A[(size_t)(i0 + r) * NN + j0 + grp + 8*t] * me[t];
        }
        tr += __shfl_xor_sync(0xffffffffu, tr, 1);
        tr += __shfl_xor_sync(0xffffffffu, tr, 2);
        tr += __shfl_xor_sync(0xffffffffu, tr, 4);
        tr += __shfl_xor_sync(0xffffffffu, tr, 8);
        tr += __shfl_xor_sync(0xffffffffu, tr, 16);
        if (lane == 0)
            g_part[(size_t)(b * NTILES + tj) * NN + i0 + r] = tr;

        // ---- col credit (off-diag): acc[jj] += A[j0+jj][i0+r]*me[jj] ----
        if (!diag) {
            #pragma unroll
            for (int t = 0; t < 4; ++t)
                colacc[t] += A[(size_t)(j0 + grp + 8*t) * NN + i0 + r] * me[t];
        }
        __syncwarp();
    }

    if (!diag) {
        if (tg == 0) {
            #pragma unroll
            for (int t = 0; t < 4; ++t) csh[wrp][grp + 8*t] = colacc[t];
        }
        __syncthreads();
        if (wrp == 0) {
            float cv = csh[0][lane] + csh[1][lane] + csh[2][lane] + csh[3][lane];
            g_part[(size_t)(b * NTILES + ti) * NN + j0 + lane] = cv;
        }
    }
}

// ---------------------------------------------------------------------------
// Kernel 3: finalize — sum 32 partials per node, node MLP.
// ---------------------------------------------------------------------------
__global__ __launch_bounds__(128) void mpnn_finalize(
    const float* __restrict__ x,
    const float* __restrict__ Wx1, const float* __restrict__ bx1,
    const float* __restrict__ Wx2, const float* __restrict__ bx2,
    const float* __restrict__ Wx3, const float* __restrict__ bx3,
    float* __restrict__ out)
{
    __shared__ float hsh[4][HH];
    const int lane = threadIdx.x & 31;
    const int wrp  = threadIdx.x >> 5;
    const int node = blockIdx.x * 4 + wrp;
    const int b    = node >> 10;
    const int i    = node & (NN - 1);

    float ps = g_part[(size_t)(b * NTILES + lane) * NN + i];
    #pragma unroll
    for (int off = 16; off; off >>= 1) ps += __shfl_xor_sync(0xffffffffu, ps, off);
    const float msum = ps;

    const float rho = x[node * 2 + 0];
    float h1b = lrelu(rho * Wx1[lane] + msum * Wx1[HH + lane] + bx1[lane]);
    hsh[wrp][lane] = h1b;
    __syncwarp();

    float h2b = bx2[lane];
    #pragma unroll
    for (int k = 0; k < HH; ++k) h2b += Wx2[k * HH + lane] * hsh[wrp][k];

    float v = lrelu(h2b) * Wx3[lane];
    #pragma unroll
    for (int off = 16; off; off >>= 1) v += __shfl_xor_sync(0xffffffffu, v, off);

    if (lane == 0) out[node] = tanhf(v + bx3[0]);
}

// ---------------------------------------------------------------------------
extern "C" void kernel_launch(void* const* d_in, const int* in_sizes, int n_in,
                              void* d_out, int out_size) {
    const float* x   = (const float*)d_in[0];
    const float* A   = (const float*)d_in[1];
    const float* Wm1 = (const float*)d_in[2];
    const float* bm1 = (const float*)d_in[3];
    const float* Wm2 = (const float*)d_in[4];
    const float* bm2 = (const float*)d_in[5];
    const float* Wm3 = (const float*)d_in[6];
    const float* bm3 = (const float*)d_in[7];
    const float* Wx1 = (const float*)d_in[8];
    const float* bx1 = (const float*)d_in[9];
    const float* Wx2 = (const float*)d_in[10];
    const float* bx2 = (const float*)d_in[11];
    const float* Wx3 = (const float*)d_in[12];
    const float* bx3 = (const float*)d_in[13];
    float* out = (float*)d_out;

    precompute_u<<<(BN * HH) / 256, 256>>>(x, Wm1, bm1);
    mpnn_pairs<<<BB * NPAIRT, 128>>>(A, Wm2, bm2, Wm3, bm3);
    mpnn_finalize<<<BN / 4, 128>>>(x, Wx1, bx1, Wx2, bx2, Wx3, bx3, out);
}